// round 6
// baseline (speedup 1.0000x reference)
#include <cuda_runtime.h>

// Problem constants (fixed shapes per reference)
#define NN  100000
#define NE  1600000
#define NG  64
#define DIN 128
#define DH  256

// ---------------- scratch (device globals; no allocation anywhere) ----------
__device__ float g_bufA[(size_t)NN * DH];   // 102.4 MB
__device__ float g_bufB[(size_t)NN * DH];   // 102.4 MB
__device__ float g_dinv[NN];
__device__ int   g_deg[NN];
__device__ int   g_rowptr[NN + 1];
__device__ int   g_cursor[NN];
__device__ int   g_src[NE];
__device__ float g_w[NE];
__device__ int   g_gstart[NG + 1];

// ---------------- CSR build ----------------
__global__ void k_zero_deg() {
    int i = blockIdx.x * 256 + threadIdx.x;
    if (i < NN) g_deg[i] = 0;
}

__global__ void k_count(const int* __restrict__ col) {
    int e = blockIdx.x * 256 + threadIdx.x;
    if (e < NE) atomicAdd(&g_deg[col[e]], 1);
}

// Single-block exclusive scan over degrees -> rowptr, cursor.
__global__ void k_scan() {
    __shared__ int sums[1024];
    int t = threadIdx.x;
    const int C = (NN + 1023) / 1024;  // 98
    int base = t * C, s = 0;
    for (int i = 0; i < C; i++) {
        int idx = base + i;
        if (idx < NN) s += g_deg[idx];
    }
    sums[t] = s;
    __syncthreads();
    // Hillis-Steele inclusive scan
    for (int off = 1; off < 1024; off <<= 1) {
        int v = sums[t];
        if (t >= off) v += sums[t - off];
        __syncthreads();
        sums[t] = v;
        __syncthreads();
    }
    int run = sums[t] - s;  // exclusive base for this chunk
    for (int i = 0; i < C; i++) {
        int idx = base + i;
        if (idx < NN) {
            g_rowptr[idx] = run;
            g_cursor[idx] = run;
            run += g_deg[idx];
        }
    }
    if (t == 1023) g_rowptr[NN] = sums[1023];
}

__global__ void k_dinv() {
    int i = blockIdx.x * 256 + threadIdx.x;
    if (i < NN) g_dinv[i] = rsqrtf((float)(g_deg[i] + 1));  // +1 self-loop
}

__global__ void k_fill(const int* __restrict__ row, const int* __restrict__ col) {
    int e = blockIdx.x * 256 + threadIdx.x;
    if (e < NE) {
        int r = row[e], c = col[e];
        int pos = atomicAdd(&g_cursor[c], 1);
        g_src[pos] = r;
        g_w[pos]   = g_dinv[r];
    }
}

// ---------------- fp32 GEMM: C[M,256] = A[M,K] @ W[K,256] ----------------
// 64x64 tile, BK=16, 256 threads, 4x4 microtile.
template <int K>
__launch_bounds__(256)
__global__ void k_gemm(const float* __restrict__ A, const float* __restrict__ W,
                       float* __restrict__ Cout) {
    __shared__ __align__(16) float As[16][68];  // [k][m], padded row (272B, 16B-aligned)
    __shared__ __align__(16) float Bs[16][68];  // [k][n]
    int tid = threadIdx.x;
    int tx = tid & 15, ty = tid >> 4;
    int m0 = blockIdx.x * 64, n0 = blockIdx.y * 64;
    float acc[4][4] = {};

    for (int k0 = 0; k0 < K; k0 += 16) {
        // A tile: 64 rows x 16 k -> 256 float4, one per thread, stored transposed
        {
            int r = tid >> 2, c4 = tid & 3;
            int gr = m0 + r;
            float4 v = make_float4(0.f, 0.f, 0.f, 0.f);
            if (gr < NN) v = *(const float4*)&A[(size_t)gr * K + k0 + c4 * 4];
            As[c4 * 4 + 0][r] = v.x;
            As[c4 * 4 + 1][r] = v.y;
            As[c4 * 4 + 2][r] = v.z;
            As[c4 * 4 + 3][r] = v.w;
        }
        // B tile: 16 k x 64 n -> 256 float4
        {
            int r = tid >> 4, c4 = tid & 15;
            *(float4*)&Bs[r][c4 * 4] =
                *(const float4*)&W[(size_t)(k0 + r) * DH + n0 + c4 * 4];
        }
        __syncthreads();
#pragma unroll
        for (int k = 0; k < 16; k++) {
            float4 av = *(const float4*)&As[k][ty * 4];
            float4 bv = *(const float4*)&Bs[k][tx * 4];
            float a[4] = {av.x, av.y, av.z, av.w};
            float b[4] = {bv.x, bv.y, bv.z, bv.w};
#pragma unroll
            for (int i = 0; i < 4; i++)
#pragma unroll
                for (int j = 0; j < 4; j++) acc[i][j] = fmaf(a[i], b[j], acc[i][j]);
        }
        __syncthreads();
    }
#pragma unroll
    for (int i = 0; i < 4; i++) {
        int gm = m0 + ty * 4 + i;
        if (gm < NN)
            *(float4*)&Cout[(size_t)gm * DH + n0 + tx * 4] =
                make_float4(acc[i][0], acc[i][1], acc[i][2], acc[i][3]);
    }
}

// ---------------- node-parallel GCN aggregation + bias + ReLU ----------------
// One block per destination node; thread d owns feature d.
__launch_bounds__(256)
__global__ void k_agg(const float* __restrict__ h, const float* __restrict__ bias,
                      float* __restrict__ out) {
    __shared__ int   ssrc[256];
    __shared__ float sw[256];
    int c = blockIdx.x, d = threadIdx.x;
    int beg = g_rowptr[c], end = g_rowptr[c + 1];
    float dc = g_dinv[c];
    float acc = h[(size_t)c * DH + d] * dc;  // self-loop: h[c]*dinv[c] (x dc below)
    for (int b = beg; b < end; b += 256) {
        int n = min(256, end - b);
        __syncthreads();
        if (d < n) {
            ssrc[d] = g_src[b + d];
            sw[d]   = g_w[b + d];
        }
        __syncthreads();
#pragma unroll 4
        for (int i = 0; i < n; i++)
            acc = fmaf(h[(size_t)ssrc[i] * DH + d], sw[i], acc);
    }
    acc = fmaf(acc, dc, bias[d]);
    out[(size_t)c * DH + d] = fmaxf(acc, 0.f);
}

// ---------------- pooling ----------------
__global__ void k_bounds(const int* __restrict__ batch) {
    int g = threadIdx.x;
    if (g <= NG) {
        int lo = 0, hi = NN;
        while (lo < hi) {
            int mid = (lo + hi) >> 1;
            if (batch[mid] < g) lo = mid + 1; else hi = mid;
        }
        g_gstart[g] = lo;
    }
}

__launch_bounds__(256)
__global__ void k_pool(const float* __restrict__ h, float* __restrict__ out) {
    int g = blockIdx.x, d = threadIdx.x;
    int beg = g_gstart[g], end = g_gstart[g + 1];
    float s0 = 0.f, s1 = 0.f, s2 = 0.f, s3 = 0.f;
    int i = beg;
    for (; i + 3 < end; i += 4) {
        s0 += h[(size_t)i * DH + d];
        s1 += h[(size_t)(i + 1) * DH + d];
        s2 += h[(size_t)(i + 2) * DH + d];
        s3 += h[(size_t)(i + 3) * DH + d];
    }
    for (; i < end; i++) s0 += h[(size_t)i * DH + d];
    float s = (s0 + s1) + (s2 + s3);
    int cnt = end - beg;
    out[g * DH + d] = s / fmaxf((float)cnt, 1.f);
}

// ---------------- launch ----------------
extern "C" void kernel_launch(void* const* d_in, const int* in_sizes, int n_in,
                              void* d_out, int out_size) {
    const float* x     = (const float*)d_in[0];
    const int*   ei    = (const int*)d_in[1];
    const int*   batch = (const int*)d_in[2];
    const float* W1    = (const float*)d_in[3];
    const float* b1    = (const float*)d_in[4];
    const float* W2    = (const float*)d_in[5];
    const float* b2    = (const float*)d_in[6];
    float*       out   = (float*)d_out;

    const int* row = ei;       // edge_index[0] = source
    const int* col = ei + NE;  // edge_index[1] = target

    float *bufA, *bufB;
    cudaGetSymbolAddress((void**)&bufA, g_bufA);
    cudaGetSymbolAddress((void**)&bufB, g_bufB);

    int nb_nodes = (NN + 255) / 256;
    int nb_edges = (NE + 255) / 256;

    // CSR build (fully re-run every call: graph-replay safe)
    k_zero_deg<<<nb_nodes, 256>>>();
    k_count<<<nb_edges, 256>>>(col);
    k_scan<<<1, 1024>>>();
    k_dinv<<<nb_nodes, 256>>>();
    k_fill<<<nb_edges, 256>>>(row, col);
    k_bounds<<<1, 128>>>(batch);

    dim3 g1((NN + 63) / 64, DH / 64);
    // Layer 1: h = x @ W1 ; agg + b1 + relu
    k_gemm<DIN><<<g1, 256>>>(x, W1, bufB);
    k_agg<<<NN, 256>>>(bufB, b1, bufA);
    // Layer 2: h = h @ W2 ; agg + b2 + relu
    k_gemm<DH><<<g1, 256>>>(bufA, W2, bufB);
    k_agg<<<NN, 256>>>(bufB, b2, bufA);
    // Global mean pool
    k_pool<<<NG, 256>>>(bufA, out);
}

// round 7
// speedup vs baseline: 1.8242x; 1.8242x over previous
#include <cuda_runtime.h>

// Problem constants (fixed shapes per reference)
#define NN  100000
#define NE  1600000
#define NG  64
#define DIN 128
#define DH  256
#define PCH 16   // pool chunks per graph

// ---------------- scratch (device globals; no allocation anywhere) ----------
__device__ float g_bufA[(size_t)NN * DH];   // 102.4 MB
__device__ float g_bufB[(size_t)NN * DH];   // 102.4 MB
__device__ float g_dinv[NN];
__device__ int   g_deg[NN];
__device__ int   g_rowptr[NN + 1];
__device__ int   g_cursor[NN];
__device__ int   g_src[NE];
__device__ float g_w[NE];
__device__ int   g_gstart[NG + 1];
__device__ float g_pp[NG * PCH * DH];       // pool partials (1 MB)

// ---------------- CSR build ----------------
__global__ void k_zero_deg() {
    int i = blockIdx.x * 256 + threadIdx.x;
    if (i < NN) g_deg[i] = 0;
}

__global__ void k_count(const int* __restrict__ col) {
    int e = blockIdx.x * 256 + threadIdx.x;
    if (e < NE) atomicAdd(&g_deg[col[e]], 1);
}

// Single-block exclusive scan over degrees -> rowptr, cursor.
__global__ void k_scan() {
    __shared__ int sums[1024];
    int t = threadIdx.x;
    const int C = (NN + 1023) / 1024;  // 98
    int base = t * C, s = 0;
    for (int i = 0; i < C; i++) {
        int idx = base + i;
        if (idx < NN) s += g_deg[idx];
    }
    sums[t] = s;
    __syncthreads();
    for (int off = 1; off < 1024; off <<= 1) {
        int v = sums[t];
        if (t >= off) v += sums[t - off];
        __syncthreads();
        sums[t] = v;
        __syncthreads();
    }
    int run = sums[t] - s;  // exclusive base for this chunk
    for (int i = 0; i < C; i++) {
        int idx = base + i;
        if (idx < NN) {
            g_rowptr[idx] = run;
            g_cursor[idx] = run;
            run += g_deg[idx];
        }
    }
    if (t == 1023) g_rowptr[NN] = sums[1023];
}

__global__ void k_dinv() {
    int i = blockIdx.x * 256 + threadIdx.x;
    if (i < NN) g_dinv[i] = rsqrtf((float)(g_deg[i] + 1));  // +1 self-loop
}

__global__ void k_fill(const int* __restrict__ row, const int* __restrict__ col) {
    int e = blockIdx.x * 256 + threadIdx.x;
    if (e < NE) {
        int r = row[e], c = col[e];
        int pos = atomicAdd(&g_cursor[c], 1);
        g_src[pos] = r;
        g_w[pos]   = g_dinv[r];
    }
}

// ---------------- node-parallel GCN aggregation (pre-linear) ----------------
// out[c] = dinv[c] * ( sum_{src->c} dinv[src]*h[src]  +  dinv[c]*h[c] )
// One block per destination node; thread d owns feature d. D = 128 or 256.
template <int D>
__launch_bounds__(D)
__global__ void k_agg(const float* __restrict__ h, float* __restrict__ out) {
    __shared__ int   ssrc[D];
    __shared__ float sw[D];
    int c = blockIdx.x, d = threadIdx.x;
    int beg = g_rowptr[c], end = g_rowptr[c + 1];
    float dc = g_dinv[c];
    float a0 = h[(size_t)c * D + d] * dc;  // self-loop (x dc again at the end)
    float a1 = 0.f, a2 = 0.f, a3 = 0.f;
    for (int b = beg; b < end; b += D) {
        int n = min(D, end - b);
        __syncthreads();
        if (d < n) {
            ssrc[d] = g_src[b + d];
            sw[d]   = g_w[b + d];
        }
        __syncthreads();
        int i = 0;
        for (; i + 4 <= n; i += 4) {
            a0 = fmaf(h[(size_t)ssrc[i + 0] * D + d], sw[i + 0], a0);
            a1 = fmaf(h[(size_t)ssrc[i + 1] * D + d], sw[i + 1], a1);
            a2 = fmaf(h[(size_t)ssrc[i + 2] * D + d], sw[i + 2], a2);
            a3 = fmaf(h[(size_t)ssrc[i + 3] * D + d], sw[i + 3], a3);
        }
        for (; i < n; i++)
            a0 = fmaf(h[(size_t)ssrc[i] * D + d], sw[i], a0);
    }
    float acc = (a0 + a1) + (a2 + a3);
    out[(size_t)c * D + d] = acc * dc;
}

// ---------------- fp32 GEMM + bias + ReLU: C = relu(A[M,K] @ W[K,256] + b) --
// 128x128 tile, BK=16, 256 threads, 8x8 microtile, 2 blocks/SM.
template <int K>
__launch_bounds__(256, 2)
__global__ void k_gemm(const float* __restrict__ A, const float* __restrict__ W,
                       const float* __restrict__ bias, float* __restrict__ Cout) {
    __shared__ __align__(16) float As[16][132];  // [k][m]
    __shared__ __align__(16) float Bs[16][132];  // [k][n]
    int tid = threadIdx.x;
    int tx = tid & 15, ty = tid >> 4;
    int m0 = blockIdx.x * 128, n0 = blockIdx.y * 128;
    float acc[8][8] = {};

    for (int k0 = 0; k0 < K; k0 += 16) {
        // A tile: 128 rows x 16 k = 512 float4, 2 per thread, stored transposed
#pragma unroll
        for (int p = tid; p < 512; p += 256) {
            int r = p >> 2, c4 = p & 3;
            int gr = m0 + r;
            float4 v = make_float4(0.f, 0.f, 0.f, 0.f);
            if (gr < NN) v = *(const float4*)&A[(size_t)gr * K + k0 + c4 * 4];
            As[c4 * 4 + 0][r] = v.x;
            As[c4 * 4 + 1][r] = v.y;
            As[c4 * 4 + 2][r] = v.z;
            As[c4 * 4 + 3][r] = v.w;
        }
        // B tile: 16 k x 128 n = 512 float4
#pragma unroll
        for (int p = tid; p < 512; p += 256) {
            int r = p >> 5, c4 = p & 31;
            *(float4*)&Bs[r][c4 * 4] =
                *(const float4*)&W[(size_t)(k0 + r) * DH + n0 + c4 * 4];
        }
        __syncthreads();
#pragma unroll
        for (int k = 0; k < 16; k++) {
            float a[8], b[8];
            *(float4*)&a[0] = *(const float4*)&As[k][ty * 8 + 0];
            *(float4*)&a[4] = *(const float4*)&As[k][ty * 8 + 4];
            *(float4*)&b[0] = *(const float4*)&Bs[k][tx * 8 + 0];
            *(float4*)&b[4] = *(const float4*)&Bs[k][tx * 8 + 4];
#pragma unroll
            for (int i = 0; i < 8; i++)
#pragma unroll
                for (int j = 0; j < 8; j++)
                    acc[i][j] = fmaf(a[i], b[j], acc[i][j]);
        }
        __syncthreads();
    }

    // epilogue: bias + relu, vectorized stores
    float bv[8];
    *(float4*)&bv[0] = *(const float4*)&bias[n0 + tx * 8 + 0];
    *(float4*)&bv[4] = *(const float4*)&bias[n0 + tx * 8 + 4];
#pragma unroll
    for (int i = 0; i < 8; i++) {
        int gm = m0 + ty * 8 + i;
        if (gm < NN) {
            float4 v0, v1;
            v0.x = fmaxf(acc[i][0] + bv[0], 0.f);
            v0.y = fmaxf(acc[i][1] + bv[1], 0.f);
            v0.z = fmaxf(acc[i][2] + bv[2], 0.f);
            v0.w = fmaxf(acc[i][3] + bv[3], 0.f);
            v1.x = fmaxf(acc[i][4] + bv[4], 0.f);
            v1.y = fmaxf(acc[i][5] + bv[5], 0.f);
            v1.z = fmaxf(acc[i][6] + bv[6], 0.f);
            v1.w = fmaxf(acc[i][7] + bv[7], 0.f);
            *(float4*)&Cout[(size_t)gm * DH + n0 + tx * 8 + 0] = v0;
            *(float4*)&Cout[(size_t)gm * DH + n0 + tx * 8 + 4] = v1;
        }
    }
}

// ---------------- pooling (two-stage) ----------------
__global__ void k_bounds(const int* __restrict__ batch) {
    int g = threadIdx.x;
    if (g <= NG) {
        int lo = 0, hi = NN;
        while (lo < hi) {
            int mid = (lo + hi) >> 1;
            if (batch[mid] < g) lo = mid + 1; else hi = mid;
        }
        g_gstart[g] = lo;
    }
}

__launch_bounds__(256)
__global__ void k_pool1(const float* __restrict__ h) {
    int g = blockIdx.x >> 4, chunk = blockIdx.x & (PCH - 1);
    int d = threadIdx.x;
    int beg = g_gstart[g], end = g_gstart[g + 1];
    long len = end - beg;
    int c0 = beg + (int)(len * chunk / PCH);
    int c1 = beg + (int)(len * (chunk + 1) / PCH);
    float s0 = 0.f, s1 = 0.f, s2 = 0.f, s3 = 0.f;
    int i = c0;
    for (; i + 4 <= c1; i += 4) {
        s0 += h[(size_t)(i + 0) * DH + d];
        s1 += h[(size_t)(i + 1) * DH + d];
        s2 += h[(size_t)(i + 2) * DH + d];
        s3 += h[(size_t)(i + 3) * DH + d];
    }
    for (; i < c1; i++) s0 += h[(size_t)i * DH + d];
    g_pp[(size_t)blockIdx.x * DH + d] = (s0 + s1) + (s2 + s3);
}

__launch_bounds__(256)
__global__ void k_pool2(float* __restrict__ out) {
    int g = blockIdx.x, d = threadIdx.x;
    float s = 0.f;
#pragma unroll
    for (int c = 0; c < PCH; c++) s += g_pp[(size_t)(g * PCH + c) * DH + d];
    int cnt = g_gstart[g + 1] - g_gstart[g];
    out[g * DH + d] = s / fmaxf((float)cnt, 1.f);
}

// ---------------- launch ----------------
extern "C" void kernel_launch(void* const* d_in, const int* in_sizes, int n_in,
                              void* d_out, int out_size) {
    const float* x     = (const float*)d_in[0];
    const int*   ei    = (const int*)d_in[1];
    const int*   batch = (const int*)d_in[2];
    const float* W1    = (const float*)d_in[3];
    const float* b1    = (const float*)d_in[4];
    const float* W2    = (const float*)d_in[5];
    const float* b2    = (const float*)d_in[6];
    float*       out   = (float*)d_out;

    const int* row = ei;       // edge_index[0] = source
    const int* col = ei + NE;  // edge_index[1] = target

    float *bufA, *bufB;
    cudaGetSymbolAddress((void**)&bufA, g_bufA);
    cudaGetSymbolAddress((void**)&bufB, g_bufB);

    int nb_nodes = (NN + 255) / 256;
    int nb_edges = (NE + 255) / 256;

    // CSR build (fully re-run every call: graph-replay safe)
    k_zero_deg<<<nb_nodes, 256>>>();
    k_count<<<nb_edges, 256>>>(col);
    k_scan<<<1, 1024>>>();
    k_dinv<<<nb_nodes, 256>>>();
    k_fill<<<nb_edges, 256>>>(row, col);
    k_bounds<<<1, 128>>>(batch);

    dim3 gg((NN + 127) / 128, DH / 128);
    // Layer 1: agg(x) [D=128] -> @W1 + b1, relu (agg commutes with linear)
    k_agg<DIN><<<NN, DIN>>>(x, bufA);
    k_gemm<DIN><<<gg, 256>>>(bufA, W1, b1, bufB);
    // Layer 2: agg(h1) [D=256] -> @W2 + b2, relu
    k_agg<DH><<<NN, DH>>>(bufB, bufA);
    k_gemm<DH><<<gg, 256>>>(bufA, W2, b2, bufB);
    // Global mean pool (two-stage)
    k_pool1<<<NG * PCH, 256>>>(bufB);
    k_pool2<<<NG, 256>>>(out);
}

// round 8
// speedup vs baseline: 2.8625x; 1.5692x over previous
#include <cuda_runtime.h>
#include <cuda_bf16.h>
#include <mma.h>

using namespace nvcuda;

// Problem constants (fixed shapes per reference)
#define NN  100000
#define NE  1600000
#define NG  64
#define DIN 128
#define DH  256
#define PCH 16   // pool chunks per graph

// ---------------- scratch (device globals; no allocation anywhere) ----------
__device__ __align__(16) float g_bufA[(size_t)NN * DH];   // 102.4 MB
__device__ __align__(16) float g_bufB[(size_t)NN * DH];   // 102.4 MB
__device__ float g_dinv[NN];
__device__ int   g_deg[NN];
__device__ int   g_rowptr[NN + 1];
__device__ int   g_cursor[NN];
__device__ int   g_src[NE];
__device__ float g_w[NE];
__device__ int   g_gstart[NG + 1];
__device__ float g_pp[NG * PCH * DH];       // pool partials (1 MB)

// ---------------- CSR build ----------------
__global__ void k_zero_deg() {
    int i = blockIdx.x * 256 + threadIdx.x;
    if (i < NN) g_deg[i] = 0;
}

__global__ void k_count(const int* __restrict__ col) {
    int e = blockIdx.x * 256 + threadIdx.x;
    if (e < NE) atomicAdd(&g_deg[col[e]], 1);
}

// Single-block exclusive scan over degrees -> rowptr, cursor.
__global__ void k_scan() {
    __shared__ int sums[1024];
    int t = threadIdx.x;
    const int C = (NN + 1023) / 1024;  // 98
    int base = t * C, s = 0;
    for (int i = 0; i < C; i++) {
        int idx = base + i;
        if (idx < NN) s += g_deg[idx];
    }
    sums[t] = s;
    __syncthreads();
    for (int off = 1; off < 1024; off <<= 1) {
        int v = sums[t];
        if (t >= off) v += sums[t - off];
        __syncthreads();
        sums[t] = v;
        __syncthreads();
    }
    int run = sums[t] - s;  // exclusive base for this chunk
    for (int i = 0; i < C; i++) {
        int idx = base + i;
        if (idx < NN) {
            g_rowptr[idx] = run;
            g_cursor[idx] = run;
            run += g_deg[idx];
        }
    }
    if (t == 1023) g_rowptr[NN] = sums[1023];
}

__global__ void k_dinv() {
    int i = blockIdx.x * 256 + threadIdx.x;
    if (i < NN) g_dinv[i] = rsqrtf((float)(g_deg[i] + 1));  // +1 self-loop
}

__global__ void k_fill(const int* __restrict__ row, const int* __restrict__ col) {
    int e = blockIdx.x * 256 + threadIdx.x;
    if (e < NE) {
        int r = row[e], c = col[e];
        int pos = atomicAdd(&g_cursor[c], 1);
        g_src[pos] = r;
        g_w[pos]   = g_dinv[r];
    }
}

// ---------------- node-parallel GCN aggregation (pre-linear, float4) -------
// out[c] = dinv[c] * ( sum_{src->c} dinv[src]*h[src]  +  dinv[c]*h[c] )
// One block per destination node; thread d owns a float4 of features.
template <int D>
__launch_bounds__(D / 4)
__global__ void k_agg(const float4* __restrict__ h4, float4* __restrict__ out4) {
    const int V = D / 4;
    __shared__ int   ssrc[V];
    __shared__ float sw[V];
    int c = blockIdx.x, d = threadIdx.x;
    int beg = g_rowptr[c], end = g_rowptr[c + 1];
    float dc = g_dinv[c];
    float4 self = h4[(size_t)c * V + d];
    float4 A0 = make_float4(self.x * dc, self.y * dc, self.z * dc, self.w * dc);
    float4 A1 = make_float4(0.f, 0.f, 0.f, 0.f);
    for (int b = beg; b < end; b += V) {
        int n = min(V, end - b);
        __syncthreads();
        if (d < n) {
            ssrc[d] = g_src[b + d];
            sw[d]   = g_w[b + d];
        }
        __syncthreads();
        int i = 0;
        for (; i + 2 <= n; i += 2) {
            float4 v0 = h4[(size_t)ssrc[i + 0] * V + d];
            float4 v1 = h4[(size_t)ssrc[i + 1] * V + d];
            float w0 = sw[i + 0], w1 = sw[i + 1];
            A0.x = fmaf(v0.x, w0, A0.x); A0.y = fmaf(v0.y, w0, A0.y);
            A0.z = fmaf(v0.z, w0, A0.z); A0.w = fmaf(v0.w, w0, A0.w);
            A1.x = fmaf(v1.x, w1, A1.x); A1.y = fmaf(v1.y, w1, A1.y);
            A1.z = fmaf(v1.z, w1, A1.z); A1.w = fmaf(v1.w, w1, A1.w);
        }
        if (i < n) {
            float4 v0 = h4[(size_t)ssrc[i] * V + d];
            float w0 = sw[i];
            A0.x = fmaf(v0.x, w0, A0.x); A0.y = fmaf(v0.y, w0, A0.y);
            A0.z = fmaf(v0.z, w0, A0.z); A0.w = fmaf(v0.w, w0, A0.w);
        }
    }
    float4 r;
    r.x = (A0.x + A1.x) * dc;
    r.y = (A0.y + A1.y) * dc;
    r.z = (A0.z + A1.z) * dc;
    r.w = (A0.w + A1.w) * dc;
    out4[(size_t)c * V + d] = r;
}

// ---------------- tensor-core GEMM (bf16x2 split) + bias + ReLU ------------
// C[M,256] = relu(A[M,K] @ W[K,256] + b), fp32 in/out, bf16 hi/lo split with
// 3 MMAs per product term (error ~2^-17, far under tolerance).
// 128x128 tile, BK=16, 8 warps (each 32x64 = 2x4 m16n16k16 fragments).
__device__ __forceinline__ void bf16_split(float a, __nv_bfloat16& hi, __nv_bfloat16& lo) {
    hi = __float2bfloat16(a);
    lo = __float2bfloat16(a - __bfloat162float(hi));
}

template <int K>
__launch_bounds__(256, 2)
__global__ void k_gemm_tc(const float* __restrict__ A, const float* __restrict__ W,
                          const float* __restrict__ bias, float* __restrict__ Cout) {
    __shared__ __align__(16) __nv_bfloat16 Ah[128][24], Al[128][24];   // [m][k]
    __shared__ __align__(16) __nv_bfloat16 Bh[16][136], Bl[16][136];   // [k][n]
    __shared__ __align__(16) float scr[8][256];                        // per-warp 16x16 stage

    int tid = threadIdx.x, wid = tid >> 5, lane = tid & 31;
    int m0 = blockIdx.x * 128, n0 = blockIdx.y * 128;
    int wm = wid >> 1, wn = wid & 1;   // warp tile: rows wm*32, cols wn*64

    wmma::fragment<wmma::accumulator, 16, 16, 16, float> acc[2][4];
#pragma unroll
    for (int mi = 0; mi < 2; mi++)
#pragma unroll
        for (int ni = 0; ni < 4; ni++) wmma::fill_fragment(acc[mi][ni], 0.0f);

    for (int k0 = 0; k0 < K; k0 += 16) {
        // A tile: 128x16 fp32 -> bf16 hi/lo (512 float4, 2 per thread)
#pragma unroll
        for (int p = tid; p < 512; p += 256) {
            int r = p >> 2, c4 = (p & 3) * 4;
            int gr = m0 + r;
            float4 v = make_float4(0.f, 0.f, 0.f, 0.f);
            if (gr < NN) v = *(const float4*)&A[(size_t)gr * K + k0 + c4];
            __nv_bfloat16 h_, l_;
            bf16_split(v.x, h_, l_); Ah[r][c4 + 0] = h_; Al[r][c4 + 0] = l_;
            bf16_split(v.y, h_, l_); Ah[r][c4 + 1] = h_; Al[r][c4 + 1] = l_;
            bf16_split(v.z, h_, l_); Ah[r][c4 + 2] = h_; Al[r][c4 + 2] = l_;
            bf16_split(v.w, h_, l_); Ah[r][c4 + 3] = h_; Al[r][c4 + 3] = l_;
        }
        // B tile: 16x128 fp32 -> bf16 hi/lo
#pragma unroll
        for (int p = tid; p < 512; p += 256) {
            int r = p >> 5, c4 = (p & 31) * 4;
            float4 v = *(const float4*)&W[(size_t)(k0 + r) * DH + n0 + c4];
            __nv_bfloat16 h_, l_;
            bf16_split(v.x, h_, l_); Bh[r][c4 + 0] = h_; Bl[r][c4 + 0] = l_;
            bf16_split(v.y, h_, l_); Bh[r][c4 + 1] = h_; Bl[r][c4 + 1] = l_;
            bf16_split(v.z, h_, l_); Bh[r][c4 + 2] = h_; Bl[r][c4 + 2] = l_;
            bf16_split(v.w, h_, l_); Bh[r][c4 + 3] = h_; Bl[r][c4 + 3] = l_;
        }
        __syncthreads();

        wmma::fragment<wmma::matrix_a, 16, 16, 16, __nv_bfloat16, wmma::row_major> ah[2], al[2];
#pragma unroll
        for (int mi = 0; mi < 2; mi++) {
            wmma::load_matrix_sync(ah[mi], &Ah[wm * 32 + mi * 16][0], 24);
            wmma::load_matrix_sync(al[mi], &Al[wm * 32 + mi * 16][0], 24);
        }
#pragma unroll
        for (int ni = 0; ni < 4; ni++) {
            wmma::fragment<wmma::matrix_b, 16, 16, 16, __nv_bfloat16, wmma::row_major> bh, bl;
            wmma::load_matrix_sync(bh, &Bh[0][wn * 64 + ni * 16], 136);
            wmma::load_matrix_sync(bl, &Bl[0][wn * 64 + ni * 16], 136);
#pragma unroll
            for (int mi = 0; mi < 2; mi++) {
                wmma::mma_sync(acc[mi][ni], ah[mi], bh, acc[mi][ni]);
                wmma::mma_sync(acc[mi][ni], al[mi], bh, acc[mi][ni]);
                wmma::mma_sync(acc[mi][ni], ah[mi], bl, acc[mi][ni]);
            }
        }
        __syncthreads();
    }

    // Epilogue: stage each 16x16 fragment through smem, add bias, relu, store.
    int er = lane >> 1, ec = (lane & 1) * 8;
#pragma unroll
    for (int mi = 0; mi < 2; mi++) {
#pragma unroll
        for (int ni = 0; ni < 4; ni++) {
            wmma::store_matrix_sync(&scr[wid][0], acc[mi][ni], 16, wmma::mem_row_major);
            __syncwarp();
            int gm = m0 + wm * 32 + mi * 16 + er;
            int gn = n0 + wn * 64 + ni * 16 + ec;
            if (gm < NN) {
                float4 b0 = *(const float4*)&bias[gn + 0];
                float4 b1 = *(const float4*)&bias[gn + 4];
                const float* s = &scr[wid][er * 16 + ec];
                float4 o0, o1;
                o0.x = fmaxf(s[0] + b0.x, 0.f); o0.y = fmaxf(s[1] + b0.y, 0.f);
                o0.z = fmaxf(s[2] + b0.z, 0.f); o0.w = fmaxf(s[3] + b0.w, 0.f);
                o1.x = fmaxf(s[4] + b1.x, 0.f); o1.y = fmaxf(s[5] + b1.y, 0.f);
                o1.z = fmaxf(s[6] + b1.z, 0.f); o1.w = fmaxf(s[7] + b1.w, 0.f);
                *(float4*)&Cout[(size_t)gm * DH + gn + 0] = o0;
                *(float4*)&Cout[(size_t)gm * DH + gn + 4] = o1;
            }
            __syncwarp();
        }
    }
}

// ---------------- pooling (two-stage) ----------------
__global__ void k_bounds(const int* __restrict__ batch) {
    int g = threadIdx.x;
    if (g <= NG) {
        int lo = 0, hi = NN;
        while (lo < hi) {
            int mid = (lo + hi) >> 1;
            if (batch[mid] < g) lo = mid + 1; else hi = mid;
        }
        g_gstart[g] = lo;
    }
}

__launch_bounds__(256)
__global__ void k_pool1(const float* __restrict__ h) {
    int g = blockIdx.x >> 4, chunk = blockIdx.x & (PCH - 1);
    int d = threadIdx.x;
    int beg = g_gstart[g], end = g_gstart[g + 1];
    long len = end - beg;
    int c0 = beg + (int)(len * chunk / PCH);
    int c1 = beg + (int)(len * (chunk + 1) / PCH);
    float s0 = 0.f, s1 = 0.f, s2 = 0.f, s3 = 0.f;
    int i = c0;
    for (; i + 4 <= c1; i += 4) {
        s0 += h[(size_t)(i + 0) * DH + d];
        s1 += h[(size_t)(i + 1) * DH + d];
        s2 += h[(size_t)(i + 2) * DH + d];
        s3 += h[(size_t)(i + 3) * DH + d];
    }
    for (; i < c1; i++) s0 += h[(size_t)i * DH + d];
    g_pp[(size_t)blockIdx.x * DH + d] = (s0 + s1) + (s2 + s3);
}

__launch_bounds__(256)
__global__ void k_pool2(float* __restrict__ out) {
    int g = blockIdx.x, d = threadIdx.x;
    float s = 0.f;
#pragma unroll
    for (int c = 0; c < PCH; c++) s += g_pp[(size_t)(g * PCH + c) * DH + d];
    int cnt = g_gstart[g + 1] - g_gstart[g];
    out[g * DH + d] = s / fmaxf((float)cnt, 1.f);
}

// ---------------- launch ----------------
extern "C" void kernel_launch(void* const* d_in, const int* in_sizes, int n_in,
                              void* d_out, int out_size) {
    const float* x     = (const float*)d_in[0];
    const int*   ei    = (const int*)d_in[1];
    const int*   batch = (const int*)d_in[2];
    const float* W1    = (const float*)d_in[3];
    const float* b1    = (const float*)d_in[4];
    const float* W2    = (const float*)d_in[5];
    const float* b2    = (const float*)d_in[6];
    float*       out   = (float*)d_out;

    const int* row = ei;       // edge_index[0] = source
    const int* col = ei + NE;  // edge_index[1] = target

    float *bufA, *bufB;
    cudaGetSymbolAddress((void**)&bufA, g_bufA);
    cudaGetSymbolAddress((void**)&bufB, g_bufB);

    int nb_nodes = (NN + 255) / 256;
    int nb_edges = (NE + 255) / 256;

    // CSR build (fully re-run every call: graph-replay safe)
    k_zero_deg<<<nb_nodes, 256>>>();
    k_count<<<nb_edges, 256>>>(col);
    k_scan<<<1, 1024>>>();
    k_dinv<<<nb_nodes, 256>>>();
    k_fill<<<nb_edges, 256>>>(row, col);
    k_bounds<<<1, 128>>>(batch);

    dim3 gg((NN + 127) / 128, DH / 128);
    // Layer 1: agg(x) [D=128] -> @W1 + b1, relu (agg commutes with linear)
    k_agg<DIN><<<NN, DIN / 4>>>((const float4*)x, (float4*)bufA);
    k_gemm_tc<DIN><<<gg, 256>>>(bufA, W1, b1, bufB);
    // Layer 2: agg(h1) [D=256] -> @W2 + b2, relu
    k_agg<DH><<<NN, DH / 4>>>((const float4*)bufB, (float4*)bufA);
    k_gemm_tc<DH><<<gg, 256>>>(bufA, W2, b2, bufB);
    // Global mean pool (two-stage)
    k_pool1<<<NG * PCH, 256>>>(bufB);
    k_pool2<<<NG, 256>>>(out);
}

// round 10
// speedup vs baseline: 3.4567x; 1.2076x over previous
#include <cuda_runtime.h>
#include <cuda_bf16.h>
#include <mma.h>

using namespace nvcuda;

// Problem constants (fixed shapes per reference)
#define NN  100000
#define NE  1600000
#define NG  64
#define DIN 128
#define DH  256
#define PCH 16   // pool chunks per graph

// ---------------- scratch (device globals; no allocation anywhere) ----------
__device__ __align__(16) __nv_bfloat16 g_hA[(size_t)NN * DH];  // 51.2 MB
__device__ __align__(16) __nv_bfloat16 g_hB[(size_t)NN * DH];  // 51.2 MB
__device__ float g_dinv[NN];
__device__ int   g_deg[NN];
__device__ int   g_rowptr[NN + 1];
__device__ int   g_cursor[NN];
__device__ int   g_src[NE];
__device__ float g_w[NE];
__device__ int   g_gstart[NG + 1];
__device__ float g_pp[NG * PCH * DH];       // pool partials (1 MB)

// ---------------- CSR build ----------------
__global__ void k_zero_deg() {
    int i = blockIdx.x * 256 + threadIdx.x;
    if (i < NN) g_deg[i] = 0;
}

__global__ void k_count(const int* __restrict__ col) {
    int e = blockIdx.x * 256 + threadIdx.x;
    if (e < NE) atomicAdd(&g_deg[col[e]], 1);
}

// Single-block exclusive scan over degrees -> rowptr, cursor.
__global__ void k_scan() {
    __shared__ int sums[1024];
    int t = threadIdx.x;
    const int C = (NN + 1023) / 1024;  // 98
    int base = t * C, s = 0;
    for (int i = 0; i < C; i++) {
        int idx = base + i;
        if (idx < NN) s += g_deg[idx];
    }
    sums[t] = s;
    __syncthreads();
    for (int off = 1; off < 1024; off <<= 1) {
        int v = sums[t];
        if (t >= off) v += sums[t - off];
        __syncthreads();
        sums[t] = v;
        __syncthreads();
    }
    int run = sums[t] - s;  // exclusive base for this chunk
    for (int i = 0; i < C; i++) {
        int idx = base + i;
        if (idx < NN) {
            g_rowptr[idx] = run;
            g_cursor[idx] = run;
            run += g_deg[idx];
        }
    }
    if (t == 1023) g_rowptr[NN] = sums[1023];
}

__global__ void k_dinv() {
    int i = blockIdx.x * 256 + threadIdx.x;
    if (i < NN) g_dinv[i] = rsqrtf((float)(g_deg[i] + 1));  // +1 self-loop
}

__global__ void k_fill(const int* __restrict__ row, const int* __restrict__ col) {
    int e = blockIdx.x * 256 + threadIdx.x;
    if (e < NE) {
        int r = row[e], c = col[e];
        int pos = atomicAdd(&g_cursor[c], 1);
        g_src[pos] = r;
        g_w[pos]   = g_dinv[r];
    }
}

// ---------------- bf16 helpers ----------------
__device__ __forceinline__ void bf16_split(float a, __nv_bfloat16& hi, __nv_bfloat16& lo) {
    hi = __float2bfloat16(a);
    lo = __float2bfloat16(a - __bfloat162float(hi));
}

__device__ __forceinline__ void unpack8(uint4 u, float f[8]) {
    float2 t;
    t = __bfloat1622float2(*reinterpret_cast<__nv_bfloat162*>(&u.x)); f[0] = t.x; f[1] = t.y;
    t = __bfloat1622float2(*reinterpret_cast<__nv_bfloat162*>(&u.y)); f[2] = t.x; f[3] = t.y;
    t = __bfloat1622float2(*reinterpret_cast<__nv_bfloat162*>(&u.z)); f[4] = t.x; f[5] = t.y;
    t = __bfloat1622float2(*reinterpret_cast<__nv_bfloat162*>(&u.w)); f[6] = t.x; f[7] = t.y;
}

__device__ __forceinline__ uint4 pack8(const float f[8]) {
    uint4 u;
    *reinterpret_cast<__nv_bfloat162*>(&u.x) = __floats2bfloat162_rn(f[0], f[1]);
    *reinterpret_cast<__nv_bfloat162*>(&u.y) = __floats2bfloat162_rn(f[2], f[3]);
    *reinterpret_cast<__nv_bfloat162*>(&u.z) = __floats2bfloat162_rn(f[4], f[5]);
    *reinterpret_cast<__nv_bfloat162*>(&u.w) = __floats2bfloat162_rn(f[6], f[7]);
    return u;
}

// ---------------- aggregation, layer 1: fp32 x -> bf16 a1 (D=128) ----------
// out[c] = dinv[c] * ( sum_{src->c} dinv[src]*h[src] + dinv[c]*h[c] )
// Warp per node; thread d owns 4 features (float4).
__launch_bounds__(32)
__global__ void k_agg1(const float4* __restrict__ x4, __nv_bfloat162* __restrict__ out2) {
    __shared__ int   ssrc[32];
    __shared__ float sw[32];
    int c = blockIdx.x, d = threadIdx.x;
    int beg = g_rowptr[c], end = g_rowptr[c + 1];
    float dc = g_dinv[c];
    float4 self = x4[(size_t)c * 32 + d];
    float a0 = self.x * dc, a1 = self.y * dc, a2 = self.z * dc, a3 = self.w * dc;
    float b0 = 0.f, b1 = 0.f, b2 = 0.f, b3 = 0.f;
    for (int b = beg; b < end; b += 32) {
        int n = min(32, end - b);
        __syncwarp();
        if (d < n) { ssrc[d] = g_src[b + d]; sw[d] = g_w[b + d]; }
        __syncwarp();
        int i = 0;
        for (; i + 2 <= n; i += 2) {
            float4 v0 = x4[(size_t)ssrc[i + 0] * 32 + d];
            float4 v1 = x4[(size_t)ssrc[i + 1] * 32 + d];
            float w0 = sw[i + 0], w1 = sw[i + 1];
            a0 = fmaf(v0.x, w0, a0); a1 = fmaf(v0.y, w0, a1);
            a2 = fmaf(v0.z, w0, a2); a3 = fmaf(v0.w, w0, a3);
            b0 = fmaf(v1.x, w1, b0); b1 = fmaf(v1.y, w1, b1);
            b2 = fmaf(v1.z, w1, b2); b3 = fmaf(v1.w, w1, b3);
        }
        if (i < n) {
            float4 v0 = x4[(size_t)ssrc[i] * 32 + d];
            float w0 = sw[i];
            a0 = fmaf(v0.x, w0, a0); a1 = fmaf(v0.y, w0, a1);
            a2 = fmaf(v0.z, w0, a2); a3 = fmaf(v0.w, w0, a3);
        }
    }
    float r0 = (a0 + b0) * dc, r1 = (a1 + b1) * dc;
    float r2 = (a2 + b2) * dc, r3 = (a3 + b3) * dc;
    out2[(size_t)c * 64 + 2 * d + 0] = __floats2bfloat162_rn(r0, r1);
    out2[(size_t)c * 64 + 2 * d + 1] = __floats2bfloat162_rn(r2, r3);
}

// ---------------- aggregation, layer 2: bf16 h1 -> bf16 a2 (D=256) ---------
// Warp per node; thread d owns 8 features (uint4 = 8 bf16).
__launch_bounds__(32)
__global__ void k_agg2(const uint4* __restrict__ h, uint4* __restrict__ out) {
    __shared__ int   ssrc[32];
    __shared__ float sw[32];
    int c = blockIdx.x, d = threadIdx.x;
    int beg = g_rowptr[c], end = g_rowptr[c + 1];
    float dc = g_dinv[c];
    float acc[8], f[8], g[8];
    unpack8(h[(size_t)c * 32 + d], f);
#pragma unroll
    for (int j = 0; j < 8; j++) acc[j] = f[j] * dc;
    for (int b = beg; b < end; b += 32) {
        int n = min(32, end - b);
        __syncwarp();
        if (d < n) { ssrc[d] = g_src[b + d]; sw[d] = g_w[b + d]; }
        __syncwarp();
        int i = 0;
        for (; i + 2 <= n; i += 2) {
            uint4 u0 = h[(size_t)ssrc[i + 0] * 32 + d];
            uint4 u1 = h[(size_t)ssrc[i + 1] * 32 + d];
            float w0 = sw[i + 0], w1 = sw[i + 1];
            unpack8(u0, f); unpack8(u1, g);
#pragma unroll
            for (int j = 0; j < 8; j++) acc[j] = fmaf(f[j], w0, acc[j]);
#pragma unroll
            for (int j = 0; j < 8; j++) acc[j] = fmaf(g[j], w1, acc[j]);
        }
        if (i < n) {
            uint4 u0 = h[(size_t)ssrc[i] * 32 + d];
            float w0 = sw[i];
            unpack8(u0, f);
#pragma unroll
            for (int j = 0; j < 8; j++) acc[j] = fmaf(f[j], w0, acc[j]);
        }
    }
#pragma unroll
    for (int j = 0; j < 8; j++) acc[j] *= dc;
    out[(size_t)c * 32 + d] = pack8(acc);
}

// ---------------- tensor-core GEMM + bias + ReLU ----------------
// C[M,256] = relu(A[M,K](bf16) @ W[K,256](fp32, hi/lo split) + b) -> bf16
// BM=128, BN=256 (full width, A staged once), BK=32, 512 threads (16 warps,
// each 32x64 = 2x4 m16n16k16 fragments, 2 MMAs per fragment: Ah*Bh + Ah*Bl).
template <int K>
__launch_bounds__(512)
__global__ void k_gemm_tc(const __nv_bfloat16* __restrict__ A, const float* __restrict__ W,
                          const float* __restrict__ bias, __nv_bfloat16* __restrict__ Cout) {
    // union-aliased smem: tiles (44032 B) vs epilogue scratch (16 KB)
    __shared__ __align__(16) unsigned char smraw[10240 + 16896 + 16896];
    __nv_bfloat16 (*As)[40]  = (__nv_bfloat16(*)[40])(smraw);                 // [128][40]
    __nv_bfloat16 (*Bh)[264] = (__nv_bfloat16(*)[264])(smraw + 10240);        // [32][264]
    __nv_bfloat16 (*Bl)[264] = (__nv_bfloat16(*)[264])(smraw + 10240 + 16896);// [32][264]
    float* scr = (float*)smraw;                                               // [16][256]

    int tid = threadIdx.x, wid = tid >> 5, lane = tid & 31;
    int m0 = blockIdx.x * 128;
    int wm = wid >> 2, wn = wid & 3;  // warp tile: rows wm*32, cols wn*64

    wmma::fragment<wmma::accumulator, 16, 16, 16, float> acc[2][4];
#pragma unroll
    for (int mi = 0; mi < 2; mi++)
#pragma unroll
        for (int ni = 0; ni < 4; ni++) wmma::fill_fragment(acc[mi][ni], 0.0f);

    for (int k0 = 0; k0 < K; k0 += 32) {
        // A tile: 128x32 bf16 (one uint4 = 8 bf16 per thread)
        {
            int r = tid >> 2, c8 = (tid & 3) * 8;
            int gr = m0 + r;
            uint4 v = make_uint4(0u, 0u, 0u, 0u);
            if (gr < NN) v = *(const uint4*)&A[(size_t)gr * K + k0 + c8];
            *(uint4*)&As[r][c8] = v;
        }
        // B tile: 32x256 fp32 -> bf16 hi/lo (4 float4 per thread)
#pragma unroll
        for (int it = 0; it < 4; it++) {
            int p = tid + it * 512;
            int r = p >> 6, c4 = (p & 63) * 4;
            float4 v = *(const float4*)&W[(size_t)(k0 + r) * DH + c4];
            __nv_bfloat16 h0, h1, h2, h3, l0, l1, l2, l3;
            bf16_split(v.x, h0, l0); bf16_split(v.y, h1, l1);
            bf16_split(v.z, h2, l2); bf16_split(v.w, h3, l3);
            __nv_bfloat162 t;
            t.x = h0; t.y = h1; *reinterpret_cast<__nv_bfloat162*>(&Bh[r][c4 + 0]) = t;
            t.x = h2; t.y = h3; *reinterpret_cast<__nv_bfloat162*>(&Bh[r][c4 + 2]) = t;
            t.x = l0; t.y = l1; *reinterpret_cast<__nv_bfloat162*>(&Bl[r][c4 + 0]) = t;
            t.x = l2; t.y = l3; *reinterpret_cast<__nv_bfloat162*>(&Bl[r][c4 + 2]) = t;
        }
        __syncthreads();

#pragma unroll
        for (int ks = 0; ks < 2; ks++) {
            wmma::fragment<wmma::matrix_a, 16, 16, 16, __nv_bfloat16, wmma::row_major> ah[2];
#pragma unroll
            for (int mi = 0; mi < 2; mi++)
                wmma::load_matrix_sync(ah[mi], &As[wm * 32 + mi * 16][ks * 16], 40);
#pragma unroll
            for (int ni = 0; ni < 4; ni++) {
                wmma::fragment<wmma::matrix_b, 16, 16, 16, __nv_bfloat16, wmma::row_major> bh, bl;
                wmma::load_matrix_sync(bh, &Bh[ks * 16][wn * 64 + ni * 16], 264);
                wmma::load_matrix_sync(bl, &Bl[ks * 16][wn * 64 + ni * 16], 264);
#pragma unroll
                for (int mi = 0; mi < 2; mi++) {
                    wmma::mma_sync(acc[mi][ni], ah[mi], bh, acc[mi][ni]);
                    wmma::mma_sync(acc[mi][ni], ah[mi], bl, acc[mi][ni]);
                }
            }
        }
        __syncthreads();
    }

    // Epilogue: stage 16x16 fragments through per-warp smem, bias+relu, bf16 store.
    float* myscr = scr + wid * 256;
    int er = lane >> 1, ec = (lane & 1) * 8;
#pragma unroll
    for (int mi = 0; mi < 2; mi++) {
#pragma unroll
        for (int ni = 0; ni < 4; ni++) {
            wmma::store_matrix_sync(myscr, acc[mi][ni], 16, wmma::mem_row_major);
            __syncwarp();
            int gm = m0 + wm * 32 + mi * 16 + er;
            int gn = wn * 64 + ni * 16 + ec;
            if (gm < NN) {
                float4 b0 = *(const float4*)&bias[gn + 0];
                float4 b1 = *(const float4*)&bias[gn + 4];
                const float* s = &myscr[er * 16 + ec];
                float o[8];
                o[0] = fmaxf(s[0] + b0.x, 0.f); o[1] = fmaxf(s[1] + b0.y, 0.f);
                o[2] = fmaxf(s[2] + b0.z, 0.f); o[3] = fmaxf(s[3] + b0.w, 0.f);
                o[4] = fmaxf(s[4] + b1.x, 0.f); o[5] = fmaxf(s[5] + b1.y, 0.f);
                o[6] = fmaxf(s[6] + b1.z, 0.f); o[7] = fmaxf(s[7] + b1.w, 0.f);
                *(uint4*)&Cout[(size_t)gm * DH + gn] = pack8(o);
            }
            __syncwarp();
        }
    }
}

// ---------------- pooling (two-stage, bf16 input) ----------------
__global__ void k_bounds(const int* __restrict__ batch) {
    int g = threadIdx.x;
    if (g <= NG) {
        int lo = 0, hi = NN;
        while (lo < hi) {
            int mid = (lo + hi) >> 1;
            if (batch[mid] < g) lo = mid + 1; else hi = mid;
        }
        g_gstart[g] = lo;
    }
}

__launch_bounds__(128)
__global__ void k_pool1(const __nv_bfloat162* __restrict__ h2) {
    int g = blockIdx.x >> 4, chunk = blockIdx.x & (PCH - 1);
    int d = threadIdx.x;  // owns features 2d, 2d+1
    int beg = g_gstart[g], end = g_gstart[g + 1];
    long len = end - beg;
    int c0 = beg + (int)(len * chunk / PCH);
    int c1 = beg + (int)(len * (chunk + 1) / PCH);
    float sx0 = 0.f, sy0 = 0.f, sx1 = 0.f, sy1 = 0.f;
    int i = c0;
    for (; i + 2 <= c1; i += 2) {
        float2 f0 = __bfloat1622float2(h2[(size_t)(i + 0) * 128 + d]);
        float2 f1 = __bfloat1622float2(h2[(size_t)(i + 1) * 128 + d]);
        sx0 += f0.x; sy0 += f0.y;
        sx1 += f1.x; sy1 += f1.y;
    }
    if (i < c1) {
        float2 f0 = __bfloat1622float2(h2[(size_t)i * 128 + d]);
        sx0 += f0.x; sy0 += f0.y;
    }
    g_pp[(size_t)blockIdx.x * DH + 2 * d + 0] = sx0 + sx1;
    g_pp[(size_t)blockIdx.x * DH + 2 * d + 1] = sy0 + sy1;
}

__launch_bounds__(256)
__global__ void k_pool2(float* __restrict__ out) {
    int g = blockIdx.x, d = threadIdx.x;
    float s = 0.f;
#pragma unroll
    for (int c = 0; c < PCH; c++) s += g_pp[(size_t)(g * PCH + c) * DH + d];
    int cnt = g_gstart[g + 1] - g_gstart[g];
    out[g * DH + d] = s / fmaxf((float)cnt, 1.f);
}

// ---------------- launch ----------------
extern "C" void kernel_launch(void* const* d_in, const int* in_sizes, int n_in,
                              void* d_out, int out_size) {
    const float* x     = (const float*)d_in[0];
    const int*   ei    = (const int*)d_in[1];
    const int*   batch = (const int*)d_in[2];
    const float* W1    = (const float*)d_in[3];
    const float* b1    = (const float*)d_in[4];
    const float* W2    = (const float*)d_in[5];
    const float* b2    = (const float*)d_in[6];
    float*       out   = (float*)d_out;

    const int* row = ei;       // edge_index[0] = source
    const int* col = ei + NE;  // edge_index[1] = target

    __nv_bfloat16 *hA, *hB;
    cudaGetSymbolAddress((void**)&hA, g_hA);
    cudaGetSymbolAddress((void**)&hB, g_hB);

    int nb_nodes = (NN + 255) / 256;
    int nb_edges = (NE + 255) / 256;

    // CSR build (fully re-run every call: graph-replay safe)
    k_zero_deg<<<nb_nodes, 256>>>();
    k_count<<<nb_edges, 256>>>(col);
    k_scan<<<1, 1024>>>();
    k_dinv<<<nb_nodes, 256>>>();
    k_fill<<<nb_edges, 256>>>(row, col);
    k_bounds<<<1, 128>>>(batch);

    int gm = (NN + 127) / 128;  // 782
    // Layer 1: agg(x) [D=128] -> @W1 + b1, relu (agg commutes with linear)
    k_agg1<<<NN, 32>>>((const float4*)x, (__nv_bfloat162*)hA);
    k_gemm_tc<DIN><<<gm, 512>>>(hA, W1, b1, hB);
    // Layer 2: agg(h1) [D=256] -> @W2 + b2, relu
    k_agg2<<<NN, 32>>>((const uint4*)hB, (uint4*)hA);
    k_gemm_tc<DH><<<gm, 512>>>(hA, W2, b2, hB);
    // Global mean pool (two-stage)
    k_pool1<<<NG * PCH, 128>>>((const __nv_bfloat162*)hB);
    k_pool2<<<NG, 256>>>(out);
}